// round 13
// baseline (speedup 1.0000x reference)
#include <cuda_runtime.h>
#include <cuda_fp16.h>

// gnn_42460046688469 — Fourier-graph gather + complex weighted aggregate + permuted scatter.
//
// R13 = R12 (138.0us best) + two changes:
//  1. Main loop rewritten with packed fma.rn.f32x2 and a SPLIT ACCUMULATOR:
//     accR = sum wr*x, accI = sum wi*x on packed (re,im) f32x2 lanes
//     (2 FFMA2 per gathered half2 instead of 4 scalar FFMA, no lane swap);
//     one final combine per channel: re = accR.re - accI.im, im = accR.im
//     + accI.re. ptxas never auto-fuses FFMA2 — PTX only. Register clamp
//     relaxed (launch_bounds(256) only) to avoid spills at ~44 regs.
//  2. repack + repack2 merged into ONE prologue launch (branch on blockIdx).
//
// Core (R6-R12): per-launch repack of Xf into an interleaved fp16 table
// (64 B/row, 67 MB) + per-node 64B pack records [idx[8]|{wr,wi}fp16[8]];
// content-based interface detection; indices clamped; output layout from
// out_size; all stores bounded.

#define K_NB 8

struct Cfg { int u; int is64; int niSel; int imagFirst; };
__device__ Cfg g_cfg;

// Interleaved fp16 complex table: up to 1,048,576 rows x 64 B (67 MB).
__device__ __align__(16) uint4 g_scratch[4194304];
// Packed per-node records: up to 524,288 nodes x 64 B (34 MB).
__device__ __align__(16) uint4 g_pack[2097152];

__global__ void detect_kernel(const unsigned* __restrict__ m0,
                              const unsigned* __restrict__ m1,
                              const unsigned* __restrict__ m2,
                              const unsigned* __restrict__ hind,
                              int s_mid, int s_hi)
{
    __shared__ int sOk[3];
    __shared__ int sZeros;
    __shared__ unsigned sVmax;
    __shared__ int sIs64;

    int tid = threadIdx.x;
    if (tid < 3) sOk[tid] = 1;
    if (tid == 3) sZeros = 0;
    if (tid == 4) sVmax = 0u;
    __syncthreads();

    int Wm = s_mid >> 2;   // words provably in-bounds under both unit schemes
    int Wh = s_hi >> 2;

    if (tid < 192) {
        int b = tid >> 6;
        int j = tid & 63;
        int step = Wm / 67; if (step < 1) step = 1;
        const unsigned* ms = (b == 0) ? m0 : (b == 1) ? m1 : m2;
        unsigned v = ms[(j * step + j) % Wm];
        if (v >= 0x01000000u) atomicExch(&sOk[b], 0);
    } else {
        int j = tid - 192;
        int step = Wh / 67; if (step < 1) step = 1;
        int w = ((j * step + j) % Wh) | 1;
        if (hind[w] == 0u) atomicAdd(&sZeros, 1);
    }
    __syncthreads();
    if (tid == 0) sIs64 = (sZeros >= 48) ? 1 : 0;
    __syncthreads();

    if (tid >= 192) {
        int j = tid - 192;
        int step = Wh / 67; if (step < 1) step = 1;
        int w = (j * step + j) % Wh;
        if (sIs64) w &= ~1;
        atomicMax(&sVmax, hind[w]);
    }
    __syncthreads();

    if (tid == 0) {
        int niSel = 2;
        if (sOk[0] && !sOk[2]) niSel = 0;
        else if (sOk[1] && !sOk[0] && !sOk[2]) niSel = 1;
        int imagFirst = (niSel == 0) ? 1 : 0;

        unsigned thresh = sIs64 ? (unsigned)(s_hi >> 3) : (unsigned)(s_hi >> 2);
        int u = (sVmax >= thresh) ? 1 : 4;

        Cfg c; c.u = u; c.is64 = sIs64; c.niSel = niSel; c.imagFirst = imagFirst;
        g_cfg = c;
    }
}

__device__ __forceinline__ int load_idx(const void* p, int off, int is64) {
    return is64 ? (int)((const long long*)p)[off] : ((const int*)p)[off];
}

// Merged prologue: blocks [0, nRepackBlocks) build the fp16 table;
// the rest build the per-node pack records.
__global__ void __launch_bounds__(256) prologue_kernel(
    const float* __restrict__ xf0, const float* __restrict__ xf1,
    const void* __restrict__ m0, const void* __restrict__ m1,
    const void* __restrict__ m2,
    int s_max, int s_mid, int nRepackBlocks)
{
    Cfg c = g_cfg;
    int Mrows = (s_max / c.u) / 16;

    if ((int)blockIdx.x < nRepackBlocks) {
        // ---- repack: split fp32 Xf_real/Xf_imag -> interleaved __half2 ----
        int i = blockIdx.x * 256 + threadIdx.x;
        if (i >= Mrows * 4) return;

        const float4* R = (const float4*)(c.imagFirst ? xf1 : xf0);
        const float4* I = (const float4*)(c.imagFirst ? xf0 : xf1);
        float4 xr = __ldg(R + i);
        float4 xi = __ldg(I + i);

        __half2 h0 = __floats2half2_rn(xr.x, xi.x);
        __half2 h1 = __floats2half2_rn(xr.y, xi.y);
        __half2 h2 = __floats2half2_rn(xr.z, xi.z);
        __half2 h3 = __floats2half2_rn(xr.w, xi.w);

        uint4 o;
        o.x = *reinterpret_cast<unsigned*>(&h0);
        o.y = *reinterpret_cast<unsigned*>(&h1);
        o.z = *reinterpret_cast<unsigned*>(&h2);
        o.w = *reinterpret_cast<unsigned*>(&h3);
        g_scratch[i] = o;
    } else {
        // ---- repack2: (NI, w_real, w_imag) -> 64B per-node records ----
        int N = (s_mid / c.u) / K_NB;
        int n = (blockIdx.x - nRepackBlocks) * 256 + threadIdx.x;
        if (n >= N) return;

        const void* mids[3] = { m0, m1, m2 };
        const void* NIp = mids[c.niSel];
        const void* wa  = (c.niSel == 0) ? m1 : m0;
        const void* wb  = (c.niSel == 2) ? m1 : m2;
        const float* wR = (const float*)(c.imagFirst ? wb : wa);
        const float* wI = (const float*)(c.imagFirst ? wa : wb);

        unsigned idxA[8]; unsigned hwA[8];
        #pragma unroll
        for (int k = 0; k < K_NB; ++k) {
            int off = k * N + n;
            unsigned idx = (unsigned)load_idx(NIp, off, c.is64);
            idxA[k] = min(idx, (unsigned)(Mrows - 1));
            __half2 hw = __floats2half2_rn(__ldg(wR + off), __ldg(wI + off));
            hwA[k] = *reinterpret_cast<unsigned*>(&hw);
        }

        uint4* P = g_pack + (size_t)n * 4;
        P[0] = make_uint4(idxA[0], idxA[1], idxA[2], idxA[3]);
        P[1] = make_uint4(idxA[4], idxA[5], idxA[6], idxA[7]);
        P[2] = make_uint4(hwA[0], hwA[1], hwA[2], hwA[3]);
        P[3] = make_uint4(hwA[4], hwA[5], hwA[6], hwA[7]);
    }
}

// ---- packed f32x2 helpers ----

// half2 (a,b) -> packed f32x2 register pair (a,b)
__device__ __forceinline__ unsigned long long h2f2_pair(unsigned h) {
    unsigned long long r;
    asm("{\n\t.reg .b16 lo, hi;\n\t.reg .f32 f0, f1;\n\t"
        "mov.b32 {lo, hi}, %1;\n\t"
        "cvt.f32.f16 f0, lo;\n\tcvt.f32.f16 f1, hi;\n\t"
        "mov.b64 %0, {f0, f1};\n\t}"
        : "=l"(r) : "r"(h));
    return r;
}

// half2 (wr,wi) -> broadcast pairs (wr,wr) and (wi,wi)
__device__ __forceinline__ void w_pairs(unsigned h,
                                        unsigned long long& wrr,
                                        unsigned long long& wii) {
    asm("{\n\t.reg .b16 lo, hi;\n\t.reg .f32 r, i;\n\t"
        "mov.b32 {lo, hi}, %2;\n\t"
        "cvt.f32.f16 r, lo;\n\tcvt.f32.f16 i, hi;\n\t"
        "mov.b64 %0, {r, r};\n\tmov.b64 %1, {i, i};\n\t}"
        : "=l"(wrr), "=l"(wii) : "r"(h));
}

#define FMA2(acc, a, b) \
    asm("fma.rn.f32x2 %0, %1, %2, %0;" : "+l"(acc) : "l"(a), "l"(b))

__device__ __forceinline__ float2 unpack2(unsigned long long p) {
    float2 f;
    asm("mov.b64 {%0, %1}, %2;" : "=f"(f.x), "=f"(f.y) : "l"(p));
    return f;
}

__device__ __forceinline__ float2 h2f(unsigned u) {
    __half2 h = *reinterpret_cast<__half2*>(&u);
    return __half22float2(h);
}

__global__ void __launch_bounds__(256) gnn_fourier_kernel(
    const void*  __restrict__ hmask, const void* __restrict__ hind,
    float4* __restrict__ out,
    int s_max, int s_mid, int s_hi, int s_hm, int out_count)
{
    Cfg c = g_cfg;

    int idxDiv = c.u * ((c.is64 && c.u == 4) ? 2 : 1);
    int NH     = s_hi / idxDiv;
    int H      = s_hm / idxDiv;
    int N      = (s_mid / c.u) / K_NB;
    int Mrows  = (s_max / c.u) / 16;

    int gid = blockIdx.x * blockDim.x + threadIdx.x;
    int row = gid >> 2;
    if (row >= NH) return;
    int t = gid & 3;

    unsigned src = (unsigned)load_idx(hind, row, c.is64);
    src = min(src, (unsigned)(NH - 1));

    const uint4* S = g_scratch;
    float4 a0, a1;   // interleaved (re,im) result: channels [4t, 4t+4)

    if ((int)src < N) {
        const uint4* P = g_pack + (size_t)src * 4;
        uint4 q0 = __ldg(P + 0);   // idx 0-3
        uint4 q1 = __ldg(P + 1);   // idx 4-7
        uint4 q2 = __ldg(P + 2);   // (wr,wi) fp16 pairs 0-3
        uint4 q3 = __ldg(P + 3);   // (wr,wi) fp16 pairs 4-7

        unsigned idxA[8] = { q0.x, q0.y, q0.z, q0.w, q1.x, q1.y, q1.z, q1.w };
        unsigned hwA[8]  = { q2.x, q2.y, q2.z, q2.w, q3.x, q3.y, q3.z, q3.w };

        // split accumulators: accR = sum wr*x, accI = sum wi*x (packed lanes)
        unsigned long long aR0 = 0ull, aR1 = 0ull, aR2 = 0ull, aR3 = 0ull;
        unsigned long long aI0 = 0ull, aI1 = 0ull, aI2 = 0ull, aI3 = 0ull;

        #pragma unroll
        for (int k = 0; k < K_NB; ++k) {
            unsigned long long wrr, wii;
            w_pairs(hwA[k], wrr, wii);
            uint4 v = __ldg(S + (size_t)(idxA[k] * 4u + (unsigned)t));
            unsigned long long x0 = h2f2_pair(v.x);
            unsigned long long x1 = h2f2_pair(v.y);
            unsigned long long x2 = h2f2_pair(v.z);
            unsigned long long x3 = h2f2_pair(v.w);
            FMA2(aR0, wrr, x0); FMA2(aI0, wii, x0);
            FMA2(aR1, wrr, x1); FMA2(aI1, wii, x1);
            FMA2(aR2, wrr, x2); FMA2(aI2, wii, x2);
            FMA2(aR3, wrr, x3); FMA2(aI3, wii, x3);
        }

        // combine: re = accR.re - accI.im ; im = accR.im + accI.re
        float2 r0 = unpack2(aR0), s0 = unpack2(aI0);
        float2 r1 = unpack2(aR1), s1 = unpack2(aI1);
        float2 r2 = unpack2(aR2), s2 = unpack2(aI2);
        float2 r3 = unpack2(aR3), s3 = unpack2(aI3);
        a0 = make_float4(r0.x - s0.y, r0.y + s0.x, r1.x - s1.y, r1.y + s1.x);
        a1 = make_float4(r2.x - s2.y, r2.y + s2.x, r3.x - s3.y, r3.y + s3.x);
    } else {
        unsigned hoff = min((unsigned)((int)src - N), (unsigned)(H - 1));
        unsigned idx = (unsigned)load_idx(hmask, (int)hoff, c.is64);
        idx = min(idx, (unsigned)(Mrows - 1));
        uint4 v = __ldg(S + (size_t)(idx * 4u + (unsigned)t));
        float2 f0 = h2f(v.x), f1 = h2f(v.y), f2 = h2f(v.z), f3 = h2f(v.w);
        a0 = make_float4(f0.x, f0.y, f1.x, f1.y);
        a1 = make_float4(f2.x, f2.y, f3.x, f3.y);
    }

    long long needF = (long long)NH * 32;
    int maxF4 = out_count >> 2;

    if ((long long)out_count >= needF) {
        int ob = row * 8 + t * 2;
        if (ob + 1 < maxF4) {
            out[ob]     = a0;
            out[ob + 1] = a1;
        }
    } else {
        int ob = row * 4 + t;
        if (ob < maxF4) out[ob] = make_float4(a0.x, a0.z, a1.x, a1.z);
    }
}

extern "C" void kernel_launch(void* const* d_in, const int* in_sizes, int n_in,
                              void* d_out, int out_size) {
    int smax = 0;
    for (int i = 0; i < n_in; ++i) if (in_sizes[i] > smax) smax = in_sizes[i];

    int smid = 0;
    for (int i = 0; i < n_in && !smid; ++i) {
        int s = in_sizes[i];
        if (s == smax || s <= 64) continue;
        int cnt = 0;
        for (int j = 0; j < n_in; ++j) if (in_sizes[j] == s) cnt++;
        if (cnt == 3) smid = s;
    }

    const float* xf[2] = { 0, 0 }; int nx = 0;
    const void*  mid[3] = { 0, 0, 0 }; int nm = 0;
    int hiPos = -1, hmPos = -1;
    if (smid) {
        for (int i = 0; i < n_in; ++i) {
            int s = in_sizes[i];
            if (s == smax)      { if (nx < 2) xf[nx++] = (const float*)d_in[i]; }
            else if (s == smid) { if (nm < 3) mid[nm++] = d_in[i]; }
            else if (s > 64) {
                if (hiPos < 0) hiPos = i;
                else if (s > in_sizes[hiPos]) { hmPos = hiPos; hiPos = i; }
                else hmPos = i;
            }
        }
    } else {
        int s2 = 0;
        for (int i = 0; i < n_in && !s2; ++i) {
            int s = in_sizes[i];
            if (s == smax || s <= 64) continue;
            int cnt = 0;
            for (int j = 0; j < n_in; ++j) if (in_sizes[j] == s) cnt++;
            if (cnt == 2) s2 = s;
        }
        smid = s2;
        int niPos = -1;
        for (int i = 0; i < n_in; ++i) if (in_sizes[i] == 2 * s2) niPos = i;
        int order[3], no = 0;
        for (int i = 0; i < n_in && no < 3; ++i)
            if (in_sizes[i] == s2 || i == niPos) order[no++] = i;
        for (int q = 0; q < 3; ++q) mid[q] = d_in[order[q]];
        for (int i = 0; i < n_in; ++i) {
            int s = in_sizes[i];
            if (s == smax) { if (nx < 2) xf[nx++] = (const float*)d_in[i]; }
            else if (s > 64 && s != s2 && i != niPos) {
                if (hiPos < 0) hiPos = i;
                else if (s > in_sizes[hiPos]) { hmPos = hiPos; hiPos = i; }
                else hmPos = i;
            }
        }
    }

    int s_hi = in_sizes[hiPos];
    int s_hm = in_sizes[hmPos];

    detect_kernel<<<1, 256>>>((const unsigned*)mid[0], (const unsigned*)mid[1],
                              (const unsigned*)mid[2], (const unsigned*)d_in[hiPos],
                              smid, s_hi);

    {
        long long rthreads  = (long long)smax / 4;          // repack (worst case)
        long long r2threads = (long long)smid / K_NB;       // repack2 (worst case)
        int nRepackBlocks  = (int)((rthreads + 255) / 256);
        int nRepack2Blocks = (int)((r2threads + 255) / 256);
        prologue_kernel<<<nRepackBlocks + nRepack2Blocks, 256>>>(
            xf[0], xf[1], mid[0], mid[1], mid[2], smax, smid, nRepackBlocks);
    }

    long long rows_max = s_hi;   // worst case; excess threads exit
    long long total_threads = rows_max * 4;
    int block = 256;
    long long grid = (total_threads + block - 1) / block;

    gnn_fourier_kernel<<<(int)grid, block>>>(d_in[hmPos], d_in[hiPos],
                                             (float4*)d_out,
                                             smax, smid, s_hi, s_hm, out_size);
}

// round 14
// speedup vs baseline: 1.0146x; 1.0146x over previous
#include <cuda_runtime.h>
#include <cuda_fp16.h>

// gnn_42460046688469 — Fourier-graph gather + complex weighted aggregate + permuted scatter.
//
// R14 = R12 (138.0us best) with ONE main-kernel change: unlock gather MLP.
// R12 carried __launch_bounds__(256, 8) (32-reg cap) since R4; at 32 regs
// ptxas cannot batch the 8 independent table gathers, so the k-loop ran
// load->use->load->use (MLP~2) — matching the observed "issue 50%, nothing
// saturated" latency signature. Now: __launch_bounds__(256) and an explicit
// two-phase loop (issue all 8 LDG.128 gathers into a register array, then
// the FMA chain in the SAME order as R12 -> bit-identical rel_err 2.151e-4).
// Occupancy drops (~64 regs) but per-warp MLP goes 2 -> 8.
// R13's FFMA2 rewrite + merged prologue are fully reverted (measured +22us:
// cvt/mov overhead of building f32x2 pairs swamped the FMA savings).
//
// Core (R6-R12): detect -> repack Xf to interleaved fp16 table (67 MB)
// -> repack2 to 64B per-node records [idx[8]|{wr,wi}fp16[8]] -> main.
// Content-based interface detection; indices clamped; output layout from
// out_size; all stores bounded.

#define K_NB 8

struct Cfg { int u; int is64; int niSel; int imagFirst; };
__device__ Cfg g_cfg;

// Interleaved fp16 complex table: up to 1,048,576 rows x 64 B (67 MB).
__device__ __align__(16) uint4 g_scratch[4194304];
// Packed per-node records: up to 524,288 nodes x 64 B (34 MB).
__device__ __align__(16) uint4 g_pack[2097152];

__global__ void detect_kernel(const unsigned* __restrict__ m0,
                              const unsigned* __restrict__ m1,
                              const unsigned* __restrict__ m2,
                              const unsigned* __restrict__ hind,
                              int s_mid, int s_hi)
{
    __shared__ int sOk[3];
    __shared__ int sZeros;
    __shared__ unsigned sVmax;
    __shared__ int sIs64;

    int tid = threadIdx.x;
    if (tid < 3) sOk[tid] = 1;
    if (tid == 3) sZeros = 0;
    if (tid == 4) sVmax = 0u;
    __syncthreads();

    int Wm = s_mid >> 2;   // words provably in-bounds under both unit schemes
    int Wh = s_hi >> 2;

    if (tid < 192) {
        int b = tid >> 6;
        int j = tid & 63;
        int step = Wm / 67; if (step < 1) step = 1;
        const unsigned* ms = (b == 0) ? m0 : (b == 1) ? m1 : m2;
        unsigned v = ms[(j * step + j) % Wm];
        if (v >= 0x01000000u) atomicExch(&sOk[b], 0);
    } else {
        int j = tid - 192;
        int step = Wh / 67; if (step < 1) step = 1;
        int w = ((j * step + j) % Wh) | 1;
        if (hind[w] == 0u) atomicAdd(&sZeros, 1);
    }
    __syncthreads();
    if (tid == 0) sIs64 = (sZeros >= 48) ? 1 : 0;
    __syncthreads();

    if (tid >= 192) {
        int j = tid - 192;
        int step = Wh / 67; if (step < 1) step = 1;
        int w = (j * step + j) % Wh;
        if (sIs64) w &= ~1;
        atomicMax(&sVmax, hind[w]);
    }
    __syncthreads();

    if (tid == 0) {
        int niSel = 2;
        if (sOk[0] && !sOk[2]) niSel = 0;
        else if (sOk[1] && !sOk[0] && !sOk[2]) niSel = 1;
        int imagFirst = (niSel == 0) ? 1 : 0;

        unsigned thresh = sIs64 ? (unsigned)(s_hi >> 3) : (unsigned)(s_hi >> 2);
        int u = (sVmax >= thresh) ? 1 : 4;

        Cfg c; c.u = u; c.is64 = sIs64; c.niSel = niSel; c.imagFirst = imagFirst;
        g_cfg = c;
    }
}

// Streaming repack: split fp32 Xf_real/Xf_imag -> interleaved __half2 rows.
__global__ void __launch_bounds__(256) repack_kernel(
    const float* __restrict__ xf0, const float* __restrict__ xf1, int s_max)
{
    Cfg c = g_cfg;
    int Mrows = (s_max / c.u) / 16;
    int i = blockIdx.x * blockDim.x + threadIdx.x;
    if (i >= Mrows * 4) return;

    const float4* R = (const float4*)(c.imagFirst ? xf1 : xf0);
    const float4* I = (const float4*)(c.imagFirst ? xf0 : xf1);
    float4 xr = __ldg(R + i);
    float4 xi = __ldg(I + i);

    __half2 h0 = __floats2half2_rn(xr.x, xi.x);
    __half2 h1 = __floats2half2_rn(xr.y, xi.y);
    __half2 h2 = __floats2half2_rn(xr.z, xi.z);
    __half2 h3 = __floats2half2_rn(xr.w, xi.w);

    uint4 o;
    o.x = *reinterpret_cast<unsigned*>(&h0);
    o.y = *reinterpret_cast<unsigned*>(&h1);
    o.z = *reinterpret_cast<unsigned*>(&h2);
    o.w = *reinterpret_cast<unsigned*>(&h3);
    g_scratch[i] = o;
}

__device__ __forceinline__ int load_idx(const void* p, int off, int is64) {
    return is64 ? (int)((const long long*)p)[off] : ((const int*)p)[off];
}

// Transpose (NI, w_real, w_imag) from (K,N) into per-node 64B records:
//   uint4[4]: [idx0-3][idx4-7][hw0-3][hw4-7]   hw = __half2(wr, wi)
__global__ void __launch_bounds__(256) repack2_kernel(
    const void* __restrict__ m0, const void* __restrict__ m1,
    const void* __restrict__ m2, int s_mid, int s_max)
{
    Cfg c = g_cfg;
    int N     = (s_mid / c.u) / K_NB;
    int Mrows = (s_max / c.u) / 16;
    int n = blockIdx.x * blockDim.x + threadIdx.x;
    if (n >= N) return;

    const void* mids[3] = { m0, m1, m2 };
    const void* NIp = mids[c.niSel];
    const void* wa  = (c.niSel == 0) ? m1 : m0;
    const void* wb  = (c.niSel == 2) ? m1 : m2;
    const float* wR = (const float*)(c.imagFirst ? wb : wa);
    const float* wI = (const float*)(c.imagFirst ? wa : wb);

    unsigned idxA[8]; unsigned hwA[8];
    #pragma unroll
    for (int k = 0; k < K_NB; ++k) {
        int off = k * N + n;
        unsigned idx = (unsigned)load_idx(NIp, off, c.is64);
        idxA[k] = min(idx, (unsigned)(Mrows - 1));
        __half2 hw = __floats2half2_rn(__ldg(wR + off), __ldg(wI + off));
        hwA[k] = *reinterpret_cast<unsigned*>(&hw);
    }

    uint4* P = g_pack + (size_t)n * 4;
    P[0] = make_uint4(idxA[0], idxA[1], idxA[2], idxA[3]);
    P[1] = make_uint4(idxA[4], idxA[5], idxA[6], idxA[7]);
    P[2] = make_uint4(hwA[0], hwA[1], hwA[2], hwA[3]);
    P[3] = make_uint4(hwA[4], hwA[5], hwA[6], hwA[7]);
}

__device__ __forceinline__ float2 h2f(unsigned u) {
    __half2 h = *reinterpret_cast<__half2*>(&u);
    return __half22float2(h);
}

__global__ void __launch_bounds__(256) gnn_fourier_kernel(
    const void*  __restrict__ hmask, const void* __restrict__ hind,
    float4* __restrict__ out,
    int s_max, int s_mid, int s_hi, int s_hm, int out_count)
{
    Cfg c = g_cfg;

    int idxDiv = c.u * ((c.is64 && c.u == 4) ? 2 : 1);
    int NH     = s_hi / idxDiv;
    int H      = s_hm / idxDiv;
    int N      = (s_mid / c.u) / K_NB;
    int Mrows  = (s_max / c.u) / 16;

    int gid = blockIdx.x * blockDim.x + threadIdx.x;
    int row = gid >> 2;
    if (row >= NH) return;
    int t = gid & 3;

    unsigned src = (unsigned)load_idx(hind, row, c.is64);
    src = min(src, (unsigned)(NH - 1));

    const uint4* S = g_scratch;
    float4 a0, a1;   // interleaved (re,im) accumulators: channels [4t, 4t+4)

    if ((int)src < N) {
        // one 64B half-line holds this row's entire weight set
        const uint4* P = g_pack + (size_t)src * 4;
        uint4 q0 = __ldg(P + 0);   // idx 0-3
        uint4 q1 = __ldg(P + 1);   // idx 4-7
        uint4 q2 = __ldg(P + 2);   // (wr,wi) fp16 pairs 0-3
        uint4 q3 = __ldg(P + 3);   // (wr,wi) fp16 pairs 4-7

        unsigned idxA[8] = { q0.x, q0.y, q0.z, q0.w, q1.x, q1.y, q1.z, q1.w };
        unsigned hwA[8]  = { q2.x, q2.y, q2.z, q2.w, q3.x, q3.y, q3.z, q3.w };

        // PHASE 1: issue all 8 independent gathers (MLP = 8)
        uint4 vA[8];
        #pragma unroll
        for (int k = 0; k < K_NB; ++k)
            vA[k] = __ldg(S + (long long)idxA[k] * 4 + t);

        // PHASE 2: FMA chain in the same order as R12 (bit-identical result)
        a0 = make_float4(0.f, 0.f, 0.f, 0.f);
        a1 = make_float4(0.f, 0.f, 0.f, 0.f);
        #pragma unroll
        for (int k = 0; k < K_NB; ++k) {
            float2 w = h2f(hwA[k]);
            float wr = w.x, wi = w.y;
            uint4 v = vA[k];
            float2 f0 = h2f(v.x), f1 = h2f(v.y), f2 = h2f(v.z), f3 = h2f(v.w);
            a0.x = fmaf(wr, f0.x, fmaf(-wi, f0.y, a0.x));
            a0.y = fmaf(wr, f0.y, fmaf( wi, f0.x, a0.y));
            a0.z = fmaf(wr, f1.x, fmaf(-wi, f1.y, a0.z));
            a0.w = fmaf(wr, f1.y, fmaf( wi, f1.x, a0.w));
            a1.x = fmaf(wr, f2.x, fmaf(-wi, f2.y, a1.x));
            a1.y = fmaf(wr, f2.y, fmaf( wi, f2.x, a1.y));
            a1.z = fmaf(wr, f3.x, fmaf(-wi, f3.y, a1.z));
            a1.w = fmaf(wr, f3.y, fmaf( wi, f3.x, a1.w));
        }
    } else {
        unsigned hoff = min((unsigned)((int)src - N), (unsigned)(H - 1));
        unsigned idx = (unsigned)load_idx(hmask, (int)hoff, c.is64);
        idx = min(idx, (unsigned)(Mrows - 1));
        uint4 v = __ldg(S + (long long)idx * 4 + t);
        float2 f0 = h2f(v.x), f1 = h2f(v.y), f2 = h2f(v.z), f3 = h2f(v.w);
        a0 = make_float4(f0.x, f0.y, f1.x, f1.y);
        a1 = make_float4(f2.x, f2.y, f3.x, f3.y);
    }

    long long needF = (long long)NH * 32;
    int maxF4 = out_count >> 2;

    if ((long long)out_count >= needF) {
        int ob = row * 8 + t * 2;
        if (ob + 1 < maxF4) {
            out[ob]     = a0;
            out[ob + 1] = a1;
        }
    } else {
        int ob = row * 4 + t;
        if (ob < maxF4) out[ob] = make_float4(a0.x, a0.z, a1.x, a1.z);
    }
}

extern "C" void kernel_launch(void* const* d_in, const int* in_sizes, int n_in,
                              void* d_out, int out_size) {
    int smax = 0;
    for (int i = 0; i < n_in; ++i) if (in_sizes[i] > smax) smax = in_sizes[i];

    int smid = 0;
    for (int i = 0; i < n_in && !smid; ++i) {
        int s = in_sizes[i];
        if (s == smax || s <= 64) continue;
        int cnt = 0;
        for (int j = 0; j < n_in; ++j) if (in_sizes[j] == s) cnt++;
        if (cnt == 3) smid = s;
    }

    const float* xf[2] = { 0, 0 }; int nx = 0;
    const void*  mid[3] = { 0, 0, 0 }; int nm = 0;
    int hiPos = -1, hmPos = -1;
    if (smid) {
        for (int i = 0; i < n_in; ++i) {
            int s = in_sizes[i];
            if (s == smax)      { if (nx < 2) xf[nx++] = (const float*)d_in[i]; }
            else if (s == smid) { if (nm < 3) mid[nm++] = d_in[i]; }
            else if (s > 64) {
                if (hiPos < 0) hiPos = i;
                else if (s > in_sizes[hiPos]) { hmPos = hiPos; hiPos = i; }
                else hmPos = i;
            }
        }
    } else {
        int s2 = 0;
        for (int i = 0; i < n_in && !s2; ++i) {
            int s = in_sizes[i];
            if (s == smax || s <= 64) continue;
            int cnt = 0;
            for (int j = 0; j < n_in; ++j) if (in_sizes[j] == s) cnt++;
            if (cnt == 2) s2 = s;
        }
        smid = s2;
        int niPos = -1;
        for (int i = 0; i < n_in; ++i) if (in_sizes[i] == 2 * s2) niPos = i;
        int order[3], no = 0;
        for (int i = 0; i < n_in && no < 3; ++i)
            if (in_sizes[i] == s2 || i == niPos) order[no++] = i;
        for (int q = 0; q < 3; ++q) mid[q] = d_in[order[q]];
        for (int i = 0; i < n_in; ++i) {
            int s = in_sizes[i];
            if (s == smax) { if (nx < 2) xf[nx++] = (const float*)d_in[i]; }
            else if (s > 64 && s != s2 && i != niPos) {
                if (hiPos < 0) hiPos = i;
                else if (s > in_sizes[hiPos]) { hmPos = hiPos; hiPos = i; }
                else hmPos = i;
            }
        }
    }

    int s_hi = in_sizes[hiPos];
    int s_hm = in_sizes[hmPos];

    detect_kernel<<<1, 256>>>((const unsigned*)mid[0], (const unsigned*)mid[1],
                              (const unsigned*)mid[2], (const unsigned*)d_in[hiPos],
                              smid, s_hi);

    {
        long long rthreads = (long long)smax / 4;
        int block = 256;
        long long rgrid = (rthreads + block - 1) / block;
        repack_kernel<<<(int)rgrid, block>>>(xf[0], xf[1], smax);
    }

    {
        long long nmax = (long long)smid / K_NB;   // worst case (element units)
        int block = 256;
        long long rgrid = (nmax + block - 1) / block;
        repack2_kernel<<<(int)rgrid, block>>>(mid[0], mid[1], mid[2], smid, smax);
    }

    long long rows_max = s_hi;   // worst case; excess threads exit
    long long total_threads = rows_max * 4;
    int block = 256;
    long long grid = (total_threads + block - 1) / block;

    gnn_fourier_kernel<<<(int)grid, block>>>(d_in[hmPos], d_in[hiPos],
                                             (float4*)d_out,
                                             smax, smid, s_hi, s_hm, out_size);
}

// round 15
// speedup vs baseline: 1.0508x; 1.0357x over previous
#include <cuda_runtime.h>
#include <cuda_fp16.h>

// gnn_42460046688469 — Fourier-graph gather + complex weighted aggregate + permuted scatter.
//
// R15 = R12 (138.0us best) + EXPLICIT register budget for gather MLP.
// R14's attempt (plain launch_bounds(256)) failed because ptxas chose a
// 34-reg schedule and sank the batched loads back to just-in-time use
// (8 in-flight uint4 need 32 regs of payload alone) AND lost occupancy.
// Now: __launch_bounds__(256, 4) = 64-reg cap (exactly the budget for
// 8 x uint4 payload + idx/hw arrays + accumulators), two-phase k-loop,
// and a compile-time memory barrier pinning all 8 LDG.128 ahead of the
// FMA chain. FMA order identical to R12 -> rel_err must be 2.151e-4.
//
// Core (R6-R12): detect -> repack Xf to interleaved fp16 table (67 MB)
// -> repack2 to 64B per-node records [idx[8]|{wr,wi}fp16[8]] -> main.
// Content-based interface detection; indices clamped; output layout from
// out_size; all stores bounded.

#define K_NB 8

struct Cfg { int u; int is64; int niSel; int imagFirst; };
__device__ Cfg g_cfg;

// Interleaved fp16 complex table: up to 1,048,576 rows x 64 B (67 MB).
__device__ __align__(16) uint4 g_scratch[4194304];
// Packed per-node records: up to 524,288 nodes x 64 B (34 MB).
__device__ __align__(16) uint4 g_pack[2097152];

__global__ void detect_kernel(const unsigned* __restrict__ m0,
                              const unsigned* __restrict__ m1,
                              const unsigned* __restrict__ m2,
                              const unsigned* __restrict__ hind,
                              int s_mid, int s_hi)
{
    __shared__ int sOk[3];
    __shared__ int sZeros;
    __shared__ unsigned sVmax;
    __shared__ int sIs64;

    int tid = threadIdx.x;
    if (tid < 3) sOk[tid] = 1;
    if (tid == 3) sZeros = 0;
    if (tid == 4) sVmax = 0u;
    __syncthreads();

    int Wm = s_mid >> 2;   // words provably in-bounds under both unit schemes
    int Wh = s_hi >> 2;

    if (tid < 192) {
        int b = tid >> 6;
        int j = tid & 63;
        int step = Wm / 67; if (step < 1) step = 1;
        const unsigned* ms = (b == 0) ? m0 : (b == 1) ? m1 : m2;
        unsigned v = ms[(j * step + j) % Wm];
        if (v >= 0x01000000u) atomicExch(&sOk[b], 0);
    } else {
        int j = tid - 192;
        int step = Wh / 67; if (step < 1) step = 1;
        int w = ((j * step + j) % Wh) | 1;
        if (hind[w] == 0u) atomicAdd(&sZeros, 1);
    }
    __syncthreads();
    if (tid == 0) sIs64 = (sZeros >= 48) ? 1 : 0;
    __syncthreads();

    if (tid >= 192) {
        int j = tid - 192;
        int step = Wh / 67; if (step < 1) step = 1;
        int w = (j * step + j) % Wh;
        if (sIs64) w &= ~1;
        atomicMax(&sVmax, hind[w]);
    }
    __syncthreads();

    if (tid == 0) {
        int niSel = 2;
        if (sOk[0] && !sOk[2]) niSel = 0;
        else if (sOk[1] && !sOk[0] && !sOk[2]) niSel = 1;
        int imagFirst = (niSel == 0) ? 1 : 0;

        unsigned thresh = sIs64 ? (unsigned)(s_hi >> 3) : (unsigned)(s_hi >> 2);
        int u = (sVmax >= thresh) ? 1 : 4;

        Cfg c; c.u = u; c.is64 = sIs64; c.niSel = niSel; c.imagFirst = imagFirst;
        g_cfg = c;
    }
}

// Streaming repack: split fp32 Xf_real/Xf_imag -> interleaved __half2 rows.
__global__ void __launch_bounds__(256) repack_kernel(
    const float* __restrict__ xf0, const float* __restrict__ xf1, int s_max)
{
    Cfg c = g_cfg;
    int Mrows = (s_max / c.u) / 16;
    int i = blockIdx.x * blockDim.x + threadIdx.x;
    if (i >= Mrows * 4) return;

    const float4* R = (const float4*)(c.imagFirst ? xf1 : xf0);
    const float4* I = (const float4*)(c.imagFirst ? xf0 : xf1);
    float4 xr = __ldg(R + i);
    float4 xi = __ldg(I + i);

    __half2 h0 = __floats2half2_rn(xr.x, xi.x);
    __half2 h1 = __floats2half2_rn(xr.y, xi.y);
    __half2 h2 = __floats2half2_rn(xr.z, xi.z);
    __half2 h3 = __floats2half2_rn(xr.w, xi.w);

    uint4 o;
    o.x = *reinterpret_cast<unsigned*>(&h0);
    o.y = *reinterpret_cast<unsigned*>(&h1);
    o.z = *reinterpret_cast<unsigned*>(&h2);
    o.w = *reinterpret_cast<unsigned*>(&h3);
    g_scratch[i] = o;
}

__device__ __forceinline__ int load_idx(const void* p, int off, int is64) {
    return is64 ? (int)((const long long*)p)[off] : ((const int*)p)[off];
}

// Transpose (NI, w_real, w_imag) from (K,N) into per-node 64B records:
//   uint4[4]: [idx0-3][idx4-7][hw0-3][hw4-7]   hw = __half2(wr, wi)
__global__ void __launch_bounds__(256) repack2_kernel(
    const void* __restrict__ m0, const void* __restrict__ m1,
    const void* __restrict__ m2, int s_mid, int s_max)
{
    Cfg c = g_cfg;
    int N     = (s_mid / c.u) / K_NB;
    int Mrows = (s_max / c.u) / 16;
    int n = blockIdx.x * blockDim.x + threadIdx.x;
    if (n >= N) return;

    const void* mids[3] = { m0, m1, m2 };
    const void* NIp = mids[c.niSel];
    const void* wa  = (c.niSel == 0) ? m1 : m0;
    const void* wb  = (c.niSel == 2) ? m1 : m2;
    const float* wR = (const float*)(c.imagFirst ? wb : wa);
    const float* wI = (const float*)(c.imagFirst ? wa : wb);

    unsigned idxA[8]; unsigned hwA[8];
    #pragma unroll
    for (int k = 0; k < K_NB; ++k) {
        int off = k * N + n;
        unsigned idx = (unsigned)load_idx(NIp, off, c.is64);
        idxA[k] = min(idx, (unsigned)(Mrows - 1));
        __half2 hw = __floats2half2_rn(__ldg(wR + off), __ldg(wI + off));
        hwA[k] = *reinterpret_cast<unsigned*>(&hw);
    }

    uint4* P = g_pack + (size_t)n * 4;
    P[0] = make_uint4(idxA[0], idxA[1], idxA[2], idxA[3]);
    P[1] = make_uint4(idxA[4], idxA[5], idxA[6], idxA[7]);
    P[2] = make_uint4(hwA[0], hwA[1], hwA[2], hwA[3]);
    P[3] = make_uint4(hwA[4], hwA[5], hwA[6], hwA[7]);
}

__device__ __forceinline__ float2 h2f(unsigned u) {
    __half2 h = *reinterpret_cast<__half2*>(&u);
    return __half22float2(h);
}

__global__ void __launch_bounds__(256, 4) gnn_fourier_kernel(
    const void*  __restrict__ hmask, const void* __restrict__ hind,
    float4* __restrict__ out,
    int s_max, int s_mid, int s_hi, int s_hm, int out_count)
{
    Cfg c = g_cfg;

    int idxDiv = c.u * ((c.is64 && c.u == 4) ? 2 : 1);
    int NH     = s_hi / idxDiv;
    int H      = s_hm / idxDiv;
    int N      = (s_mid / c.u) / K_NB;
    int Mrows  = (s_max / c.u) / 16;

    int gid = blockIdx.x * blockDim.x + threadIdx.x;
    int row = gid >> 2;
    if (row >= NH) return;
    int t = gid & 3;

    unsigned src = (unsigned)load_idx(hind, row, c.is64);
    src = min(src, (unsigned)(NH - 1));

    const uint4* S = g_scratch;
    float4 a0, a1;   // interleaved (re,im) accumulators: channels [4t, 4t+4)

    if ((int)src < N) {
        // one 64B half-line holds this row's entire weight set
        const uint4* P = g_pack + (size_t)src * 4;
        uint4 q0 = __ldg(P + 0);   // idx 0-3
        uint4 q1 = __ldg(P + 1);   // idx 4-7
        uint4 q2 = __ldg(P + 2);   // (wr,wi) fp16 pairs 0-3
        uint4 q3 = __ldg(P + 3);   // (wr,wi) fp16 pairs 4-7

        unsigned idxA[8] = { q0.x, q0.y, q0.z, q0.w, q1.x, q1.y, q1.z, q1.w };
        unsigned hwA[8]  = { q2.x, q2.y, q2.z, q2.w, q3.x, q3.y, q3.z, q3.w };

        // PHASE 1: issue all 8 independent gathers (MLP = 8)
        uint4 v0 = __ldg(S + (long long)idxA[0] * 4 + t);
        uint4 v1 = __ldg(S + (long long)idxA[1] * 4 + t);
        uint4 v2 = __ldg(S + (long long)idxA[2] * 4 + t);
        uint4 v3 = __ldg(S + (long long)idxA[3] * 4 + t);
        uint4 v4 = __ldg(S + (long long)idxA[4] * 4 + t);
        uint4 v5 = __ldg(S + (long long)idxA[5] * 4 + t);
        uint4 v6 = __ldg(S + (long long)idxA[6] * 4 + t);
        uint4 v7 = __ldg(S + (long long)idxA[7] * 4 + t);
        asm volatile("" ::: "memory");   // keep loads ahead of the FMA chain

        uint4 vA[8] = { v0, v1, v2, v3, v4, v5, v6, v7 };

        // PHASE 2: FMA chain in the same order as R12 (bit-identical result)
        a0 = make_float4(0.f, 0.f, 0.f, 0.f);
        a1 = make_float4(0.f, 0.f, 0.f, 0.f);
        #pragma unroll
        for (int k = 0; k < K_NB; ++k) {
            float2 w = h2f(hwA[k]);
            float wr = w.x, wi = w.y;
            uint4 v = vA[k];
            float2 f0 = h2f(v.x), f1 = h2f(v.y), f2 = h2f(v.z), f3 = h2f(v.w);
            a0.x = fmaf(wr, f0.x, fmaf(-wi, f0.y, a0.x));
            a0.y = fmaf(wr, f0.y, fmaf( wi, f0.x, a0.y));
            a0.z = fmaf(wr, f1.x, fmaf(-wi, f1.y, a0.z));
            a0.w = fmaf(wr, f1.y, fmaf( wi, f1.x, a0.w));
            a1.x = fmaf(wr, f2.x, fmaf(-wi, f2.y, a1.x));
            a1.y = fmaf(wr, f2.y, fmaf( wi, f2.x, a1.y));
            a1.z = fmaf(wr, f3.x, fmaf(-wi, f3.y, a1.z));
            a1.w = fmaf(wr, f3.y, fmaf( wi, f3.x, a1.w));
        }
    } else {
        unsigned hoff = min((unsigned)((int)src - N), (unsigned)(H - 1));
        unsigned idx = (unsigned)load_idx(hmask, (int)hoff, c.is64);
        idx = min(idx, (unsigned)(Mrows - 1));
        uint4 v = __ldg(S + (long long)idx * 4 + t);
        float2 f0 = h2f(v.x), f1 = h2f(v.y), f2 = h2f(v.z), f3 = h2f(v.w);
        a0 = make_float4(f0.x, f0.y, f1.x, f1.y);
        a1 = make_float4(f2.x, f2.y, f3.x, f3.y);
    }

    long long needF = (long long)NH * 32;
    int maxF4 = out_count >> 2;

    if ((long long)out_count >= needF) {
        int ob = row * 8 + t * 2;
        if (ob + 1 < maxF4) {
            out[ob]     = a0;
            out[ob + 1] = a1;
        }
    } else {
        int ob = row * 4 + t;
        if (ob < maxF4) out[ob] = make_float4(a0.x, a0.z, a1.x, a1.z);
    }
}

extern "C" void kernel_launch(void* const* d_in, const int* in_sizes, int n_in,
                              void* d_out, int out_size) {
    int smax = 0;
    for (int i = 0; i < n_in; ++i) if (in_sizes[i] > smax) smax = in_sizes[i];

    int smid = 0;
    for (int i = 0; i < n_in && !smid; ++i) {
        int s = in_sizes[i];
        if (s == smax || s <= 64) continue;
        int cnt = 0;
        for (int j = 0; j < n_in; ++j) if (in_sizes[j] == s) cnt++;
        if (cnt == 3) smid = s;
    }

    const float* xf[2] = { 0, 0 }; int nx = 0;
    const void*  mid[3] = { 0, 0, 0 }; int nm = 0;
    int hiPos = -1, hmPos = -1;
    if (smid) {
        for (int i = 0; i < n_in; ++i) {
            int s = in_sizes[i];
            if (s == smax)      { if (nx < 2) xf[nx++] = (const float*)d_in[i]; }
            else if (s == smid) { if (nm < 3) mid[nm++] = d_in[i]; }
            else if (s > 64) {
                if (hiPos < 0) hiPos = i;
                else if (s > in_sizes[hiPos]) { hmPos = hiPos; hiPos = i; }
                else hmPos = i;
            }
        }
    } else {
        int s2 = 0;
        for (int i = 0; i < n_in && !s2; ++i) {
            int s = in_sizes[i];
            if (s == smax || s <= 64) continue;
            int cnt = 0;
            for (int j = 0; j < n_in; ++j) if (in_sizes[j] == s) cnt++;
            if (cnt == 2) s2 = s;
        }
        smid = s2;
        int niPos = -1;
        for (int i = 0; i < n_in; ++i) if (in_sizes[i] == 2 * s2) niPos = i;
        int order[3], no = 0;
        for (int i = 0; i < n_in && no < 3; ++i)
            if (in_sizes[i] == s2 || i == niPos) order[no++] = i;
        for (int q = 0; q < 3; ++q) mid[q] = d_in[order[q]];
        for (int i = 0; i < n_in; ++i) {
            int s = in_sizes[i];
            if (s == smax) { if (nx < 2) xf[nx++] = (const float*)d_in[i]; }
            else if (s > 64 && s != s2 && i != niPos) {
                if (hiPos < 0) hiPos = i;
                else if (s > in_sizes[hiPos]) { hmPos = hiPos; hiPos = i; }
                else hmPos = i;
            }
        }
    }

    int s_hi = in_sizes[hiPos];
    int s_hm = in_sizes[hmPos];

    detect_kernel<<<1, 256>>>((const unsigned*)mid[0], (const unsigned*)mid[1],
                              (const unsigned*)mid[2], (const unsigned*)d_in[hiPos],
                              smid, s_hi);

    {
        long long rthreads = (long long)smax / 4;
        int block = 256;
        long long rgrid = (rthreads + block - 1) / block;
        repack_kernel<<<(int)rgrid, block>>>(xf[0], xf[1], smax);
    }

    {
        long long nmax = (long long)smid / K_NB;   // worst case (element units)
        int block = 256;
        long long rgrid = (nmax + block - 1) / block;
        repack2_kernel<<<(int)rgrid, block>>>(mid[0], mid[1], mid[2], smid, smax);
    }

    long long rows_max = s_hi;   // worst case; excess threads exit
    long long total_threads = rows_max * 4;
    int block = 256;
    long long grid = (total_threads + block - 1) / block;

    gnn_fourier_kernel<<<(int)grid, block>>>(d_in[hmPos], d_in[hiPos],
                                             (float4*)d_out,
                                             smax, smid, s_hi, s_hm, out_size);
}

// round 17
// speedup vs baseline: 1.2357x; 1.1759x over previous
#include <cuda_runtime.h>
#include <cuda_fp16.h>

// gnn_42460046688469 — Fourier-graph gather + complex weighted aggregate + permuted scatter.
//
// R17 = R16 RESUBMITTED UNCHANGED. R16's bench failed with "CUDA-capable
// device(s) is/are busy or unavailable" at harness init (line 253) — a
// transient broker/container acquisition failure, not a kernel fault; no
// measurement was taken. The R16 theory is still untested:
//
// R16 = R12 (138.0us best) + MIXED-PRECISION FMA (fma.rn.f32.f16) + merged prologue.
// R12's inner loop issued 16 FFMA + ~10 cvt.f32.f16 per k (conversions = 40%
// of loop instructions, 20cy latency each inside the accumulate chain).
// sm_100+ has mixed fma: f16 inputs, f32 accumulate — conversion folds into
// the FMA. Halves extracted as u16 (4cy alu ops), -wi = sign-bit XOR.
// Same op order as R12 -> numerically identical (rel_err 2.151e-4).
// Memory config = R12 (launch_bounds(256,8), plain k-loop): R14/R15 proved
// per-warp load batching only trades occupancy for nothing.
//
// Launches: detect (5us) -> prologue (repack fp16 table + pack records) -> main.

#define K_NB 8

struct Cfg { int u; int is64; int niSel; int imagFirst; };
__device__ Cfg g_cfg;

// Interleaved fp16 complex table: up to 1,048,576 rows x 64 B (67 MB).
__device__ __align__(16) uint4 g_scratch[4194304];
// Packed per-node records: up to 524,288 nodes x 64 B (34 MB).
__device__ __align__(16) uint4 g_pack[2097152];

__global__ void detect_kernel(const unsigned* __restrict__ m0,
                              const unsigned* __restrict__ m1,
                              const unsigned* __restrict__ m2,
                              const unsigned* __restrict__ hind,
                              int s_mid, int s_hi)
{
    __shared__ int sOk[3];
    __shared__ int sZeros;
    __shared__ unsigned sVmax;
    __shared__ int sIs64;

    int tid = threadIdx.x;
    if (tid < 3) sOk[tid] = 1;
    if (tid == 3) sZeros = 0;
    if (tid == 4) sVmax = 0u;
    __syncthreads();

    int Wm = s_mid >> 2;   // words provably in-bounds under both unit schemes
    int Wh = s_hi >> 2;

    if (tid < 192) {
        int b = tid >> 6;
        int j = tid & 63;
        int step = Wm / 67; if (step < 1) step = 1;
        const unsigned* ms = (b == 0) ? m0 : (b == 1) ? m1 : m2;
        unsigned v = ms[(j * step + j) % Wm];
        if (v >= 0x01000000u) atomicExch(&sOk[b], 0);
    } else {
        int j = tid - 192;
        int step = Wh / 67; if (step < 1) step = 1;
        int w = ((j * step + j) % Wh) | 1;
        if (hind[w] == 0u) atomicAdd(&sZeros, 1);
    }
    __syncthreads();
    if (tid == 0) sIs64 = (sZeros >= 48) ? 1 : 0;
    __syncthreads();

    if (tid >= 192) {
        int j = tid - 192;
        int step = Wh / 67; if (step < 1) step = 1;
        int w = (j * step + j) % Wh;
        if (sIs64) w &= ~1;
        atomicMax(&sVmax, hind[w]);
    }
    __syncthreads();

    if (tid == 0) {
        int niSel = 2;
        if (sOk[0] && !sOk[2]) niSel = 0;
        else if (sOk[1] && !sOk[0] && !sOk[2]) niSel = 1;
        int imagFirst = (niSel == 0) ? 1 : 0;

        unsigned thresh = sIs64 ? (unsigned)(s_hi >> 3) : (unsigned)(s_hi >> 2);
        int u = (sVmax >= thresh) ? 1 : 4;

        Cfg c; c.u = u; c.is64 = sIs64; c.niSel = niSel; c.imagFirst = imagFirst;
        g_cfg = c;
    }
}

__device__ __forceinline__ int load_idx(const void* p, int off, int is64) {
    return is64 ? (int)((const long long*)p)[off] : ((const int*)p)[off];
}

// Merged prologue: blocks [0, nRepackBlocks) build the fp16 table;
// the rest build the 64B per-node pack records.
__global__ void __launch_bounds__(256) prologue_kernel(
    const float* __restrict__ xf0, const float* __restrict__ xf1,
    const void* __restrict__ m0, const void* __restrict__ m1,
    const void* __restrict__ m2,
    int s_max, int s_mid, int nRepackBlocks)
{
    Cfg c = g_cfg;
    int Mrows = (s_max / c.u) / 16;

    if ((int)blockIdx.x < nRepackBlocks) {
        // ---- repack: split fp32 Xf_real/Xf_imag -> interleaved __half2 ----
        int i = blockIdx.x * 256 + threadIdx.x;
        if (i >= Mrows * 4) return;

        const float4* R = (const float4*)(c.imagFirst ? xf1 : xf0);
        const float4* I = (const float4*)(c.imagFirst ? xf0 : xf1);
        float4 xr = __ldg(R + i);
        float4 xi = __ldg(I + i);

        __half2 h0 = __floats2half2_rn(xr.x, xi.x);
        __half2 h1 = __floats2half2_rn(xr.y, xi.y);
        __half2 h2 = __floats2half2_rn(xr.z, xi.z);
        __half2 h3 = __floats2half2_rn(xr.w, xi.w);

        uint4 o;
        o.x = *reinterpret_cast<unsigned*>(&h0);
        o.y = *reinterpret_cast<unsigned*>(&h1);
        o.z = *reinterpret_cast<unsigned*>(&h2);
        o.w = *reinterpret_cast<unsigned*>(&h3);
        g_scratch[i] = o;
    } else {
        // ---- repack2: (NI, w_real, w_imag) -> 64B per-node records ----
        int N = (s_mid / c.u) / K_NB;
        int n = (blockIdx.x - nRepackBlocks) * 256 + threadIdx.x;
        if (n >= N) return;

        const void* mids[3] = { m0, m1, m2 };
        const void* NIp = mids[c.niSel];
        const void* wa  = (c.niSel == 0) ? m1 : m0;
        const void* wb  = (c.niSel == 2) ? m1 : m2;
        const float* wR = (const float*)(c.imagFirst ? wb : wa);
        const float* wI = (const float*)(c.imagFirst ? wa : wb);

        unsigned idxA[8]; unsigned hwA[8];
        #pragma unroll
        for (int k = 0; k < K_NB; ++k) {
            int off = k * N + n;
            unsigned idx = (unsigned)load_idx(NIp, off, c.is64);
            idxA[k] = min(idx, (unsigned)(Mrows - 1));
            __half2 hw = __floats2half2_rn(__ldg(wR + off), __ldg(wI + off));
            hwA[k] = *reinterpret_cast<unsigned*>(&hw);
        }

        uint4* P = g_pack + (size_t)n * 4;
        P[0] = make_uint4(idxA[0], idxA[1], idxA[2], idxA[3]);
        P[1] = make_uint4(idxA[4], idxA[5], idxA[6], idxA[7]);
        P[2] = make_uint4(hwA[0], hwA[1], hwA[2], hwA[3]);
        P[3] = make_uint4(hwA[4], hwA[5], hwA[6], hwA[7]);
    }
}

__device__ __forceinline__ float2 h2f(unsigned u) {
    __half2 h = *reinterpret_cast<__half2*>(&u);
    return __half22float2(h);
}

// mixed-precision FMA: acc (f32) += a (f16) * b (f16)   [sm_100+]
#define FMAH(acc, a, b) \
    asm("fma.rn.f32.f16 %0, %1, %2, %0;" : "+f"(acc) : "h"(a), "h"(b))

__global__ void __launch_bounds__(256, 8) gnn_fourier_kernel(
    const void*  __restrict__ hmask, const void* __restrict__ hind,
    float4* __restrict__ out,
    int s_max, int s_mid, int s_hi, int s_hm, int out_count)
{
    Cfg c = g_cfg;

    int idxDiv = c.u * ((c.is64 && c.u == 4) ? 2 : 1);
    int NH     = s_hi / idxDiv;
    int H      = s_hm / idxDiv;
    int N      = (s_mid / c.u) / K_NB;
    int Mrows  = (s_max / c.u) / 16;

    int gid = blockIdx.x * blockDim.x + threadIdx.x;
    int row = gid >> 2;
    if (row >= NH) return;
    int t = gid & 3;

    unsigned src = (unsigned)load_idx(hind, row, c.is64);
    src = min(src, (unsigned)(NH - 1));

    const uint4* S = g_scratch;
    float4 a0, a1;   // interleaved (re,im) accumulators: channels [4t, 4t+4)

    if ((int)src < N) {
        // one 64B half-line holds this row's entire weight set
        const uint4* P = g_pack + (size_t)src * 4;
        uint4 q0 = __ldg(P + 0);   // idx 0-3
        uint4 q1 = __ldg(P + 1);   // idx 4-7
        uint4 q2 = __ldg(P + 2);   // (wr,wi) fp16 pairs 0-3
        uint4 q3 = __ldg(P + 3);   // (wr,wi) fp16 pairs 4-7

        unsigned idxA[8] = { q0.x, q0.y, q0.z, q0.w, q1.x, q1.y, q1.z, q1.w };
        unsigned hwA[8]  = { q2.x, q2.y, q2.z, q2.w, q3.x, q3.y, q3.z, q3.w };

        a0 = make_float4(0.f, 0.f, 0.f, 0.f);
        a1 = make_float4(0.f, 0.f, 0.f, 0.f);
        #pragma unroll
        for (int k = 0; k < K_NB; ++k) {
            unsigned hw = hwA[k];
            unsigned short wr  = (unsigned short)(hw & 0xFFFFu);
            unsigned short wi  = (unsigned short)(hw >> 16);
            unsigned short nwi = (unsigned short)(wi ^ 0x8000u);

            uint4 v = __ldg(S + (long long)idxA[k] * 4 + t);
            unsigned short re0 = (unsigned short)(v.x & 0xFFFFu);
            unsigned short im0 = (unsigned short)(v.x >> 16);
            unsigned short re1 = (unsigned short)(v.y & 0xFFFFu);
            unsigned short im1 = (unsigned short)(v.y >> 16);
            unsigned short re2 = (unsigned short)(v.z & 0xFFFFu);
            unsigned short im2 = (unsigned short)(v.z >> 16);
            unsigned short re3 = (unsigned short)(v.w & 0xFFFFu);
            unsigned short im3 = (unsigned short)(v.w >> 16);

            // same op order as R12: acc = fma(wr, re, fma(-wi, im, acc)) etc.
            FMAH(a0.x, nwi, im0); FMAH(a0.x, wr, re0);
            FMAH(a0.y,  wi, re0); FMAH(a0.y, wr, im0);
            FMAH(a0.z, nwi, im1); FMAH(a0.z, wr, re1);
            FMAH(a0.w,  wi, re1); FMAH(a0.w, wr, im1);
            FMAH(a1.x, nwi, im2); FMAH(a1.x, wr, re2);
            FMAH(a1.y,  wi, re2); FMAH(a1.y, wr, im2);
            FMAH(a1.z, nwi, im3); FMAH(a1.z, wr, re3);
            FMAH(a1.w,  wi, re3); FMAH(a1.w, wr, im3);
        }
    } else {
        unsigned hoff = min((unsigned)((int)src - N), (unsigned)(H - 1));
        unsigned idx = (unsigned)load_idx(hmask, (int)hoff, c.is64);
        idx = min(idx, (unsigned)(Mrows - 1));
        uint4 v = __ldg(S + (long long)idx * 4 + t);
        float2 f0 = h2f(v.x), f1 = h2f(v.y), f2 = h2f(v.z), f3 = h2f(v.w);
        a0 = make_float4(f0.x, f0.y, f1.x, f1.y);
        a1 = make_float4(f2.x, f2.y, f3.x, f3.y);
    }

    long long needF = (long long)NH * 32;
    int maxF4 = out_count >> 2;

    if ((long long)out_count >= needF) {
        int ob = row * 8 + t * 2;
        if (ob + 1 < maxF4) {
            out[ob]     = a0;
            out[ob + 1] = a1;
        }
    } else {
        int ob = row * 4 + t;
        if (ob < maxF4) out[ob] = make_float4(a0.x, a0.z, a1.x, a1.z);
    }
}

extern "C" void kernel_launch(void* const* d_in, const int* in_sizes, int n_in,
                              void* d_out, int out_size) {
    int smax = 0;
    for (int i = 0; i < n_in; ++i) if (in_sizes[i] > smax) smax = in_sizes[i];

    int smid = 0;
    for (int i = 0; i < n_in && !smid; ++i) {
        int s = in_sizes[i];
        if (s == smax || s <= 64) continue;
        int cnt = 0;
        for (int j = 0; j < n_in; ++j) if (in_sizes[j] == s) cnt++;
        if (cnt == 3) smid = s;
    }

    const float* xf[2] = { 0, 0 }; int nx = 0;
    const void*  mid[3] = { 0, 0, 0 }; int nm = 0;
    int hiPos = -1, hmPos = -1;
    if (smid) {
        for (int i = 0; i < n_in; ++i) {
            int s = in_sizes[i];
            if (s == smax)      { if (nx < 2) xf[nx++] = (const float*)d_in[i]; }
            else if (s == smid) { if (nm < 3) mid[nm++] = d_in[i]; }
            else if (s > 64) {
                if (hiPos < 0) hiPos = i;
                else if (s > in_sizes[hiPos]) { hmPos = hiPos; hiPos = i; }
                else hmPos = i;
            }
        }
    } else {
        int s2 = 0;
        for (int i = 0; i < n_in && !s2; ++i) {
            int s = in_sizes[i];
            if (s == smax || s <= 64) continue;
            int cnt = 0;
            for (int j = 0; j < n_in; ++j) if (in_sizes[j] == s) cnt++;
            if (cnt == 2) s2 = s;
        }
        smid = s2;
        int niPos = -1;
        for (int i = 0; i < n_in; ++i) if (in_sizes[i] == 2 * s2) niPos = i;
        int order[3], no = 0;
        for (int i = 0; i < n_in && no < 3; ++i)
            if (in_sizes[i] == s2 || i == niPos) order[no++] = i;
        for (int q = 0; q < 3; ++q) mid[q] = d_in[order[q]];
        for (int i = 0; i < n_in; ++i) {
            int s = in_sizes[i];
            if (s == smax) { if (nx < 2) xf[nx++] = (const float*)d_in[i]; }
            else if (s > 64 && s != s2 && i != niPos) {
                if (hiPos < 0) hiPos = i;
                else if (s > in_sizes[hiPos]) { hmPos = hiPos; hiPos = i; }
                else hmPos = i;
            }
        }
    }

    int s_hi = in_sizes[hiPos];
    int s_hm = in_sizes[hmPos];

    detect_kernel<<<1, 256>>>((const unsigned*)mid[0], (const unsigned*)mid[1],
                              (const unsigned*)mid[2], (const unsigned*)d_in[hiPos],
                              smid, s_hi);

    {
        long long rthreads  = (long long)smax / 4;       // repack (worst case)
        long long r2threads = (long long)smid / K_NB;    // repack2 (worst case)
        int nRepackBlocks  = (int)((rthreads + 255) / 256);
        int nRepack2Blocks = (int)((r2threads + 255) / 256);
        prologue_kernel<<<nRepackBlocks + nRepack2Blocks, 256>>>(
            xf[0], xf[1], mid[0], mid[1], mid[2], smax, smid, nRepackBlocks);
    }

    long long rows_max = s_hi;   // worst case; excess threads exit
    long long total_threads = rows_max * 4;
    int block = 256;
    long long grid = (total_threads + block - 1) / block;

    gnn_fourier_kernel<<<(int)grid, block>>>(d_in[hmPos], d_in[hiPos],
                                             (float4*)d_out,
                                             smax, smid, s_hi, s_hm, out_size);
}